// round 14
// baseline (speedup 1.0000x reference)
#include <cuda_runtime.h>
#include <stdint.h>

// ---------- Kernel 1: fused output-zero + pin2node L2 prefetch ----------
// Blocks [0, zero_blocks)            : zero the 1M-float output (float4).
// Blocks [zero_blocks, grid)         : prefetch pin2node into L2, evict_last.
__global__ void prep_kernel(float* __restrict__ out, int n_out,
                            const char* __restrict__ table, long table_bytes,
                            int zero_blocks)
{
    if (blockIdx.x < (unsigned)zero_blocks) {
        int i = blockIdx.x * blockDim.x + threadIdx.x;
        float4* o4 = reinterpret_cast<float4*>(out);
        int n4 = n_out >> 2;
        if (i < n4) o4[i] = make_float4(0.f, 0.f, 0.f, 0.f);
    } else {
        long line = (long)(blockIdx.x - zero_blocks) * blockDim.x + threadIdx.x;
        long off = line * 128;
        if (off < table_bytes) {
            const char* p = table + off;
            asm volatile("prefetch.global.L2::evict_last [%0];" :: "l"(p));
        }
    }
}

// Gather load with evict_last L2 policy via cache-hint register.
__device__ __forceinline__ int ldg_evict_last(const int* p, uint64_t policy) {
    int v;
    asm volatile("ld.global.nc.L2::cache_hint.b32 %0, [%1], %2;"
                 : "=r"(v) : "l"(p), "l"(policy));
    return v;
}

// ---------- Kernel 2: scatter-add, beta fused, 2 arcs/thread ----------
__global__ void scatter_add_kernel(
    const float*  __restrict__ beta,          // [1]
    const float2* __restrict__ tnet_weights,  // [num_tnets/2] as float2
    const int4*   __restrict__ tnet2pin,      // [num_tnets/2] two (src,dst) pairs
    const int*    __restrict__ pin2node,      // [num_pins], int32
    float* __restrict__ out,                  // [num_nodes]
    int num_pairs)
{
    int i = blockIdx.x * blockDim.x + threadIdx.x;
    if (i >= num_pairs) return;

    uint64_t policy;
    asm volatile("createpolicy.fractional.L2::evict_last.b64 %0, 1.0;"
                 : "=l"(policy));

    float b = __ldg(beta);
    // Streaming (evict-first) loads: don't pollute L2.
    float2 w  = __ldcs(&tnet_weights[i]);
    int4 pins = __ldcs(&tnet2pin[i]);

    float wb0 = w.x * b;
    float wb1 = w.y * b;

    // Random gathers: table pre-pinned in L2, keep evict_last on refills.
    int n0 = ldg_evict_last(&pin2node[pins.x], policy);
    int n1 = ldg_evict_last(&pin2node[pins.y], policy);
    int n2 = ldg_evict_last(&pin2node[pins.z], policy);
    int n3 = ldg_evict_last(&pin2node[pins.w], policy);

    atomicAdd(out + n0, wb0);
    atomicAdd(out + n1, wb0);
    atomicAdd(out + n2, wb1);
    atomicAdd(out + n3, wb1);
}

extern "C" void kernel_launch(void* const* d_in, const int* in_sizes, int n_in,
                              void* d_out, int out_size)
{
    const float* beta     = (const float*)d_in[0];
    const float* tnet_w   = (const float*)d_in[1];
    const int*   flat_t2p = (const int*)d_in[2];
    const int*   pin2node = (const int*)d_in[3];
    float*       out      = (float*)d_out;

    int  num_tnets   = in_sizes[1];              // 8388608
    int  num_pins    = in_sizes[3];              // 20971520
    int  num_nodes   = out_size;                 // 1048576
    int  num_pairs   = num_tnets >> 1;
    long table_bytes = (long)num_pins * 4;       // 80 MB

    // 1) fused: zero output + prefetch-pin table into L2 (evict_last)
    {
        int threads = 256;
        int zero_blocks = ((num_nodes >> 2) + threads - 1) / threads;          // 1024
        long lines = (table_bytes + 127) / 128;                                 // 655360
        int pf_blocks = (int)((lines + threads - 1) / threads);                 // 2560
        prep_kernel<<<zero_blocks + pf_blocks, threads>>>(
            out, num_nodes, (const char*)pin2node, table_bytes, zero_blocks);
    }

    // 2) scatter-add
    {
        int threads = 256;
        int blocks = (num_pairs + threads - 1) / threads;
        scatter_add_kernel<<<blocks, threads>>>(
            beta, (const float2*)tnet_w, (const int4*)flat_t2p,
            pin2node, out, num_pairs);
    }
}

// round 15
// speedup vs baseline: 1.0146x; 1.0146x over previous
#include <cuda_runtime.h>
#include <stdint.h>

// One fused kernel used for both passes.
// Block ranges: [0,zero_blocks) zero output | [.., +pf_blocks) prefetch table
// slice | rest: process arcs whose pins fall in [lo, hi).
__global__ void fused_pass(
    const float*  __restrict__ beta,
    const float4* __restrict__ w4,        // [num_tnets/4]
    const int4*   __restrict__ pins4,     // [num_tnets/2] (2 int4 per quad)
    const int*    __restrict__ pin2node,
    float* __restrict__ out,
    int num_quads, int lo, int hi,
    int zero_blocks, int pf_blocks,
    long pf_start_byte, long pf_bytes, int n_out)
{
    unsigned b = blockIdx.x;
    if (b < (unsigned)zero_blocks) {
        int i = b * blockDim.x + threadIdx.x;
        int n4 = n_out >> 2;
        if (i < n4) reinterpret_cast<float4*>(out)[i] = make_float4(0.f,0.f,0.f,0.f);
        return;
    }
    b -= zero_blocks;
    if (b < (unsigned)pf_blocks) {
        long line = (long)b * blockDim.x + threadIdx.x;
        if (line * 128 < pf_bytes) {
            const char* p = (const char*)pin2node + pf_start_byte + line * 128;
            asm volatile("prefetch.global.L2 [%0];" :: "l"(p));
        }
        return;
    }
    b -= pf_blocks;
    int i = b * blockDim.x + threadIdx.x;
    if (i >= num_quads) return;

    float bt = __ldg(beta);
    float4 w  = __ldcs(&w4[i]);
    int4   pa = __ldcs(&pins4[2*i]);
    int4   pb = __ldcs(&pins4[2*i + 1]);

    float wb0 = w.x * bt, wb1 = w.y * bt, wb2 = w.z * bt, wb3 = w.w * bt;

    #define PROC(pin, wb)                                  \
        if ((pin) >= lo && (pin) < hi) {                   \
            int n = __ldg(&pin2node[(pin)]);               \
            atomicAdd(out + n, (wb));                      \
        }
    PROC(pa.x, wb0) PROC(pa.y, wb0)
    PROC(pa.z, wb1) PROC(pa.w, wb1)
    PROC(pb.x, wb2) PROC(pb.y, wb2)
    PROC(pb.z, wb3) PROC(pb.w, wb3)
    #undef PROC
}

extern "C" void kernel_launch(void* const* d_in, const int* in_sizes, int n_in,
                              void* d_out, int out_size)
{
    const float* beta     = (const float*)d_in[0];
    const float* tnet_w   = (const float*)d_in[1];
    const int*   flat_t2p = (const int*)d_in[2];
    const int*   pin2node = (const int*)d_in[3];
    float*       out      = (float*)d_out;

    int  num_tnets = in_sizes[1];              // 8388608
    int  num_pins  = in_sizes[3];              // 20971520
    int  num_nodes = out_size;                 // 1048576
    int  num_quads = num_tnets >> 2;           // 2097152
    int  mid       = num_pins >> 1;            // partition boundary

    const int threads = 256;
    int arc_blocks  = (num_quads + threads - 1) / threads;       // 8192
    int zero_blocks = ((num_nodes >> 2) + threads - 1) / threads; // 1024

    long half_bytes = (long)mid * 4;                              // 40 MB
    int  pf_blocks  = (int)((half_bytes / 128 + threads - 1) / threads); // 1280

    // Pass 0: zero output, prefetch table[0, mid), process pins < mid
    fused_pass<<<zero_blocks + pf_blocks + arc_blocks, threads>>>(
        beta, (const float4*)tnet_w, (const int4*)flat_t2p, pin2node, out,
        num_quads, 0, mid,
        zero_blocks, pf_blocks, 0, half_bytes, num_nodes);

    // Pass 1: prefetch table[mid, num_pins), process pins >= mid
    long rest_bytes = (long)(num_pins - mid) * 4;
    int  pf_blocks1 = (int)((rest_bytes / 128 + threads - 1) / threads);
    fused_pass<<<pf_blocks1 + arc_blocks, threads>>>(
        beta, (const float4*)tnet_w, (const int4*)flat_t2p, pin2node, out,
        num_quads, mid, num_pins,
        0, pf_blocks1, half_bytes, rest_bytes, num_nodes);
}